// round 16
// baseline (speedup 1.0000x reference)
#include <cuda_runtime.h>
#include <cuda_fp16.h>
#include <math.h>
#include <stdint.h>

#define NINT 37449
#define NVOC 32000

// ---------------- device scratch (no allocs allowed) ----------------
static __device__ __half g_Pbh[(size_t)NVOC * 128]; // emb@W_in + b_in   (fp16)
static __device__ __half g_Th [(size_t)NVOC * 128]; // tanh(Pb)          (fp16)
static __device__ __half g_Qh [(size_t)NVOC * 128]; // T@W_out           (fp16)
static __device__ __half g_hh [(size_t)NINT * 128]; // hidden, internal  (fp16)
static __device__ __half g_zero[128];               // never written -> stays zero
static __device__ uint4  g_Bfrag[2][4096];          // {Win,U}: {bh0,bh1,bl0,bl1} fp16x2 split
static __device__ uint2  g_BfragS[4096];            // Wout: single fp16 frags

// --- small-tile (M=64, K=128) smem layout ---
#define KP 68
#define SMEM_BYTES (64 * KP * 4)   // 17408

// --- level5 big-K tile (M=32, K=1024) smem layout ---
#define KCH 68                      // uint32 stride per child chunk (64 data + 4 pad)
#define KPL (8 * KCH + 4)           // 548 uint32 per row  (548 % 32 == 4)
#define SMEM_L5 (32 * KPL * 4)      // 70144 bytes

__device__ __forceinline__ uint32_t pack_h2(float v0, float v1) {
    __half2 h = __floats2half2_rn(v0, v1);
    return *(uint32_t*)&h;
}

__device__ __forceinline__ void store_k4h(uint32_t* AsH, int row, int f4, float4 v) {
    const int o = row * KP + f4 * 2;
    AsH[o]     = pack_h2(v.x, v.y);
    AsH[o + 1] = pack_h2(v.z, v.w);
}

__device__ __forceinline__ void mma16h(float d[4], const uint32_t a[4],
                                       uint32_t b0, uint32_t b1) {
    asm volatile(
        "mma.sync.aligned.m16n8k16.row.col.f32.f16.f16.f32 "
        "{%0,%1,%2,%3}, {%4,%5,%6,%7}, {%8,%9}, {%0,%1,%2,%3};"
        : "+f"(d[0]), "+f"(d[1]), "+f"(d[2]), "+f"(d[3])
        : "r"(a[0]), "r"(a[1]), "r"(a[2]), "r"(a[3]), "r"(b0), "r"(b1));
}

// 64x128x128 tile GEMM, fp16: single A x (Bhi + Blo).
__device__ __forceinline__ void gemm64h(const uint32_t* __restrict__ AsH,
                                        const uint4* __restrict__ Bf,
                                        int wr, int wc, int lane,
                                        float acc[8][4])
{
    const int rA = wr * 16 + (lane >> 2);
    const int cA = lane & 3;
#pragma unroll
    for (int ks = 0; ks < 8; ks++) {
        uint32_t ah[4];
        const int kpb = ks * 8 + cA;
        ah[0] = AsH[rA * KP + kpb];
        ah[1] = AsH[(rA + 8) * KP + kpb];
        ah[2] = AsH[rA * KP + kpb + 4];
        ah[3] = AsH[(rA + 8) * KP + kpb + 4];
#pragma unroll
        for (int nt = 0; nt < 8; nt++) {
            uint4 b = __ldg(&Bf[(ks * 16 + wc * 8 + nt) * 32 + lane]);
            mma16h(acc[nt], ah, b.x, b.y);
            mma16h(acc[nt], ah, b.z, b.w);
        }
    }
}

// 64x128x128 tile GEMM, fp16: single A x single B.
__device__ __forceinline__ void gemm64s(const uint32_t* __restrict__ AsH,
                                        const uint2* __restrict__ Bf,
                                        int wr, int wc, int lane,
                                        float acc[8][4])
{
    const int rA = wr * 16 + (lane >> 2);
    const int cA = lane & 3;
#pragma unroll
    for (int ks = 0; ks < 8; ks++) {
        uint32_t ah[4];
        const int kpb = ks * 8 + cA;
        ah[0] = AsH[rA * KP + kpb];
        ah[1] = AsH[(rA + 8) * KP + kpb];
        ah[2] = AsH[rA * KP + kpb + 4];
        ah[3] = AsH[(rA + 8) * KP + kpb + 4];
#pragma unroll
        for (int nt = 0; nt < 8; nt++) {
            uint2 b = __ldg(&Bf[(ks * 16 + wc * 8 + nt) * 32 + lane]);
            mma16h(acc[nt], ah, b.x, b.y);
        }
    }
}

#define ACC_ZERO8(acc) do { \
    _Pragma("unroll") for (int _b = 0; _b < 8; _b++) \
    _Pragma("unroll") for (int _c = 0; _c < 4; _c++) acc[_b][_c] = 0.f; } while (0)
#define ACC_ZERO4(acc) do { \
    _Pragma("unroll") for (int _b = 0; _b < 4; _b++) \
    _Pragma("unroll") for (int _c = 0; _c < 4; _c++) acc[_b][_c] = 0.f; } while (0)

// ---------------------------------------------------------------------------
// k_prep: B fragments. Win,U: fp16 2-term split. Wout: single fp16.
// ---------------------------------------------------------------------------
__global__ void k_prep(const float* __restrict__ Win, const float* __restrict__ U,
                       const float* __restrict__ Wout)
{
    int i = blockIdx.x * 256 + threadIdx.x;
    if (i < 3 * 4096) {
        int w = i >> 12, r = i & 4095;
        int ks = r >> 9, ng = (r >> 5) & 15, lane = r & 31;
        int n = ng * 8 + (lane >> 2);
        int k0 = ks * 16 + (lane & 3) * 2;
        const float* W = (w == 0) ? Win : ((w == 1) ? U : Wout);
        float v00 = W[k0 * 128 + n],       v01 = W[(k0 + 1) * 128 + n];
        float v10 = W[(k0 + 8) * 128 + n], v11 = W[(k0 + 9) * 128 + n];
        if (w < 2) {
            float h00 = __half2float(__float2half_rn(v00));
            float h01 = __half2float(__float2half_rn(v01));
            float h10 = __half2float(__float2half_rn(v10));
            float h11 = __half2float(__float2half_rn(v11));
            g_Bfrag[w][r] = make_uint4(pack_h2(h00, h01), pack_h2(h10, h11),
                                       pack_h2(v00 - h00, v01 - h01),
                                       pack_h2(v10 - h10, v11 - h11));
        } else {
            g_BfragS[r] = make_uint2(pack_h2(v00, v01), pack_h2(v10, v11));
        }
    }
}

// ---------------------------------------------------------------------------
// k_vocab1: Pb = emb@W_in + b_in; T = tanh(Pb)   (64 rows/block)
// ---------------------------------------------------------------------------
__global__ void __launch_bounds__(256, 3)
k_vocab1(const float* __restrict__ emb, const float* __restrict__ b_in)
{
    extern __shared__ uint32_t sm[];
    uint32_t* AsH = sm;

    const int tid = threadIdx.x, wid = tid >> 5, lane = tid & 31;
    const int wr = wid & 3, wc = wid >> 2;
    const int row0 = blockIdx.x * 64;

    for (int i = tid; i < 2048; i += 256) {
        int row = i >> 5, q = i & 31;
        float4 v = ((const float4*)emb)[(size_t)(row0 + row) * 32 + q];
        store_k4h(AsH, row, q, v);
    }
    __syncthreads();

    float acc[8][4];
    ACC_ZERO8(acc);
    gemm64h(AsH, g_Bfrag[0], wr, wc, lane, acc);

#pragma unroll
    for (int h = 0; h < 2; h++) {
        const size_t node = row0 + wr * 16 + (lane >> 2) + h * 8;
#pragma unroll
        for (int nt = 0; nt < 8; nt++) {
            const int col = wc * 64 + nt * 8 + (lane & 3) * 2;
            float2 b = *(const float2*)&b_in[col];
            float p0 = acc[nt][h * 2]     + b.x;
            float p1 = acc[nt][h * 2 + 1] + b.y;
            *(__half2*)&g_Pbh[node * 128 + col] = __floats2half2_rn(p0, p1);
            *(__half2*)&g_Th[node * 128 + col] =
                __floats2half2_rn(tanhf(p0), tanhf(p1));
        }
    }
}

// ---------------------------------------------------------------------------
// k_vocab2: Q = T @ W_out
// ---------------------------------------------------------------------------
__global__ void __launch_bounds__(256, 3)
k_vocab2()
{
    extern __shared__ uint32_t sm[];
    uint32_t* AsH = sm;

    const int tid = threadIdx.x, wid = tid >> 5, lane = tid & 31;
    const int wr = wid & 3, wc = wid >> 2;
    const int row0 = blockIdx.x * 64;

    for (int i = tid; i < 2048; i += 256) {
        int row = i >> 5, q = i & 31;
        uint2 v = ((const uint2*)(g_Th + (size_t)(row0 + row) * 128))[q];
        AsH[row * KP + q * 2]     = v.x;
        AsH[row * KP + q * 2 + 1] = v.y;
    }
    __syncthreads();

    float acc[8][4];
    ACC_ZERO8(acc);
    gemm64s(AsH, g_BfragS, wr, wc, lane, acc);

#pragma unroll
    for (int h = 0; h < 2; h++) {
        const size_t node = row0 + wr * 16 + (lane >> 2) + h * 8;
#pragma unroll
        for (int nt = 0; nt < 8; nt++) {
            const int col = wc * 64 + nt * 8 + (lane & 3) * 2;
            *(__half2*)&g_Qh[node * 128 + col] =
                __floats2half2_rn(acc[nt][h * 2], acc[nt][h * 2 + 1]);
        }
    }
}

// ---------------------------------------------------------------------------
// k_level5v: child-sum folded into MMA K-dim.
//   A' = [T[x_c0] | ... | T[x_c7]]  (M=32 nodes, K=1024, fp16, raw copies)
//   h  = tanh(A' @ Ustacked + Pb[x]*m);  then fused out = h @ W_out + b_out
// Warp (wr in 0..1, wc in 0..3): rows wr*16..+16, cols wc*32..+32.
// ---------------------------------------------------------------------------
__global__ void __launch_bounds__(256, 3)
k_level5v(int s, const int* __restrict__ x, const int* __restrict__ mask,
          const int* __restrict__ children, const float* __restrict__ b_out,
          float* __restrict__ out)
{
    extern __shared__ uint32_t sm[];
    uint32_t* As = sm;

    const int tid = threadIdx.x, wid = tid >> 5, lane = tid & 31;
    const int wr = wid & 1, wc = wid >> 1;
    const int row0 = blockIdx.x * 32;

    // staging: thread = one (node, child) pair; pure gather-copy, no math
    {
        const int n = tid >> 3, c = tid & 7;
        const int cc = children[(size_t)(s + row0 + n) * 8 + c];
        const int mm = mask[cc];
        const uint4* src = (const uint4*)(mm ? (g_Th + (size_t)x[cc] * 128) : g_zero);
        uint32_t* dst = As + n * KPL + c * KCH;
#pragma unroll
        for (int j = 0; j < 16; j++) {
            uint4 v = __ldg(src + j);
            dst[j * 4]     = v.x; dst[j * 4 + 1] = v.y;
            dst[j * 4 + 2] = v.z; dst[j * 4 + 3] = v.w;
        }
    }
    __syncthreads();

    // pass 1: K=1024 GEMM vs U (2-term split), B frags reused via ks&7
    float acc[4][4];
    ACC_ZERO4(acc);
    {
        const int rA = wr * 16 + (lane >> 2);
        const int cA = lane & 3;
#pragma unroll 8
        for (int ks = 0; ks < 64; ks++) {
            const int kpb = (ks >> 3) * KCH + (ks & 7) * 8 + cA;
            uint32_t ah[4];
            ah[0] = As[rA * KPL + kpb];
            ah[1] = As[(rA + 8) * KPL + kpb];
            ah[2] = As[rA * KPL + kpb + 4];
            ah[3] = As[(rA + 8) * KPL + kpb + 4];
            const int lks = ks & 7;
#pragma unroll
            for (int nt = 0; nt < 4; nt++) {
                uint4 b = __ldg(&g_Bfrag[1][(lks * 16 + wc * 4 + nt) * 32 + lane]);
                mma16h(acc[nt], ah, b.x, b.y);
                mma16h(acc[nt], ah, b.z, b.w);
            }
        }
    }

    // epilogue 1: h = tanh(acc + Pb*m); write g_hh; keep h in acc
#pragma unroll
    for (int h = 0; h < 2; h++) {
        const int node = s + row0 + wr * 16 + (lane >> 2) + h * 8;
        const float mf = (float)mask[node];
        const size_t xm = (size_t)(x[node] * mask[node]);
#pragma unroll
        for (int nt = 0; nt < 4; nt++) {
            const int col = wc * 32 + nt * 8 + (lane & 3) * 2;
            float2 p = __half22float2(*(const __half2*)&g_Pbh[xm * 128 + col]);
            float o0 = tanhf(acc[nt][h * 2]     + p.x * mf);
            float o1 = tanhf(acc[nt][h * 2 + 1] + p.y * mf);
            *(__half2*)&g_hh[(size_t)node * 128 + col] = __floats2half2_rn(o0, o1);
            acc[nt][h * 2]     = o0;
            acc[nt][h * 2 + 1] = o1;
        }
    }
    __syncthreads();
#pragma unroll
    for (int h = 0; h < 2; h++) {
        const int r = wr * 16 + (lane >> 2) + h * 8;
#pragma unroll
        for (int nt = 0; nt < 4; nt++) {
            const int col = wc * 32 + nt * 8 + (lane & 3) * 2;
            As[r * KPL + (col >> 1)] = pack_h2(acc[nt][h * 2], acc[nt][h * 2 + 1]);
        }
    }
    __syncthreads();

    // pass 2: out = h @ W_out + b_out  (K=128 in child-0 slot, single fp16 B)
    ACC_ZERO4(acc);
    {
        const int rA = wr * 16 + (lane >> 2);
        const int cA = lane & 3;
#pragma unroll
        for (int ks = 0; ks < 8; ks++) {
            const int kpb = ks * 8 + cA;
            uint32_t ah[4];
            ah[0] = As[rA * KPL + kpb];
            ah[1] = As[(rA + 8) * KPL + kpb];
            ah[2] = As[rA * KPL + kpb + 4];
            ah[3] = As[(rA + 8) * KPL + kpb + 4];
#pragma unroll
            for (int nt = 0; nt < 4; nt++) {
                uint2 b = __ldg(&g_BfragS[(ks * 16 + wc * 4 + nt) * 32 + lane]);
                mma16h(acc[nt], ah, b.x, b.y);
            }
        }
    }

#pragma unroll
    for (int h = 0; h < 2; h++) {
        const int node = s + row0 + wr * 16 + (lane >> 2) + h * 8;
#pragma unroll
        for (int nt = 0; nt < 4; nt++) {
            const int col = wc * 32 + nt * 8 + (lane & 3) * 2;
            float2 b = *(const float2*)&b_out[col];
            float2 o = make_float2(acc[nt][h * 2] + b.x,
                                   acc[nt][h * 2 + 1] + b.y);
            __stcs((float2*)&out[(size_t)node * 128 + col], o);
        }
    }
}

// ---------------------------------------------------------------------------
// k_out_t: out[r0 .. r0+nrows) = g_hh @ W_out + b_out
// ---------------------------------------------------------------------------
__global__ void __launch_bounds__(256, 3)
k_out_t(int r0, int nrows, const float* __restrict__ b_out, float* __restrict__ out)
{
    extern __shared__ uint32_t sm[];
    uint32_t* AsH = sm;

    const int tid = threadIdx.x, wid = tid >> 5, lane = tid & 31;
    const int wr = wid & 3, wc = wid >> 2;
    const int row0 = r0 + blockIdx.x * 64;
    const int e = r0 + nrows;

    for (int i = tid; i < 2048; i += 256) {
        int row = i >> 5, q = i & 31;
        int rr = row0 + row; if (rr >= e) rr = e - 1;
        uint2 v = ((const uint2*)(g_hh + (size_t)rr * 128))[q];
        AsH[row * KP + q * 2]     = v.x;
        AsH[row * KP + q * 2 + 1] = v.y;
    }
    __syncthreads();

    float acc[8][4];
    ACC_ZERO8(acc);
    gemm64s(AsH, g_BfragS, wr, wc, lane, acc);

#pragma unroll
    for (int h = 0; h < 2; h++) {
        const int node = row0 + wr * 16 + (lane >> 2) + h * 8;
        if (node < e) {
#pragma unroll
            for (int nt = 0; nt < 8; nt++) {
                const int col = wc * 64 + nt * 8 + (lane & 3) * 2;
                float2 b = *(const float2*)&b_out[col];
                float2 o = make_float2(acc[nt][h * 2] + b.x,
                                       acc[nt][h * 2 + 1] + b.y);
                __stcs((float2*)&out[(size_t)node * 128 + col], o);
            }
        }
    }
}

// ---------------------------------------------------------------------------
// node-level FFMA body: 16 nodes per block-slot, 256 threads (fp16 h table)
// ---------------------------------------------------------------------------
__device__ __forceinline__ void nodes_body(int base, int s, int e,
                                           const int* __restrict__ x,
                                           const int* __restrict__ mask,
                                           const int* __restrict__ children,
                                           const float* __restrict__ U,
                                           float (*agg)[128])
{
    const int tid = threadIdx.x;
    const int col = tid & 127, half = tid >> 7;

#pragma unroll
    for (int g = 0; g < 8; g++) {
        const int node = base + half * 8 + g;
        const int nb = (node < e) ? node : s;
        float sum = 0.f;
#pragma unroll
        for (int c = 0; c < 8; c++)
            sum += __half2float(g_hh[(size_t)children[(size_t)nb * 8 + c] * 128 + col]);
        agg[half * 8 + g][col] = sum;
    }
    __syncthreads();

    float acc[8];
#pragma unroll
    for (int g = 0; g < 8; g++) acc[g] = 0.f;
#pragma unroll 4
    for (int k = 0; k < 128; k++) {
        const float u = __ldg(&U[k * 128 + col]);
#pragma unroll
        for (int g = 0; g < 8; g++)
            acc[g] = fmaf(agg[half * 8 + g][k], u, acc[g]);
    }

#pragma unroll
    for (int g = 0; g < 8; g++) {
        const int node = base + half * 8 + g;
        if (node < e) {
            const float mf = (float)mask[node];
            const int xm = x[node] * mask[node];
            const float hin = __half2float(g_Pbh[(size_t)xm * 128 + col]) * mf;
            g_hh[(size_t)node * 128 + col] = __float2half_rn(tanhf(hin + acc[g]));
        }
    }
}

__global__ void __launch_bounds__(256, 4)
k_nodes(int s, int n, const int* __restrict__ x, const int* __restrict__ mask,
        const int* __restrict__ children, const float* __restrict__ U)
{
    __shared__ float agg[16][128];
    nodes_body(s + blockIdx.x * 16, s, s + n, x, mask, children, U, agg);
}

__global__ void __launch_bounds__(256, 1)
k_tail(const int* __restrict__ x, const int* __restrict__ mask,
       const int* __restrict__ children, const float* __restrict__ U)
{
    __shared__ float agg[16][128];
    const int ls[3] = {9, 1, 0};
    const int ln[3] = {64, 8, 1};
    for (int lv = 0; lv < 3; lv++) {
        const int s = ls[lv], e = s + ln[lv];
        for (int base = s; base < e; base += 16) {
            nodes_body(base, s, e, x, mask, children, U, agg);
            __syncthreads();
        }
    }
}

// ---------------------------------------------------------------------------
// k_out_leaf: out[leaf] = mask * Q[x] + b_out
// ---------------------------------------------------------------------------
__global__ void __launch_bounds__(256)
k_out_leaf(const int* __restrict__ x, const int* __restrict__ mask,
           const float* __restrict__ b_out, float* __restrict__ out)
{
    const float4 bv = ((const float4*)b_out)[threadIdx.x & 31];
    int idx = blockIdx.x * 256 + threadIdx.x;
#pragma unroll
    for (int it = 0; it < 4; it++, idx += 8192 * 256) {
        const int rr = idx >> 5, c = idx & 31;
        const int node = NINT + rr;
        const int m = mask[node];
        const int xm = x[node] * m;
        const float mf = (float)m;
        uint2 qw = *(const uint2*)(g_Qh + (size_t)xm * 128 + c * 4);
        float2 q0 = __half22float2(*(const __half2*)&qw.x);
        float2 q1 = __half22float2(*(const __half2*)&qw.y);
        float4 o = make_float4(fmaf(q0.x, mf, bv.x), fmaf(q0.y, mf, bv.y),
                               fmaf(q1.x, mf, bv.z), fmaf(q1.y, mf, bv.w));
        __stcs(&((float4*)out)[(size_t)node * 32 + c], o);
    }
}

// ---------------------------------------------------------------------------
extern "C" void kernel_launch(void* const* d_in, const int* in_sizes, int n_in,
                              void* d_out, int out_size)
{
    const int*   x        = (const int*)  d_in[0];
    const int*   mask     = (const int*)  d_in[1];
    const int*   children = (const int*)  d_in[2];
    const float* emb      = (const float*)d_in[3];
    const float* W_in     = (const float*)d_in[4];
    const float* b_in     = (const float*)d_in[5];
    const float* U        = (const float*)d_in[6];
    const float* W_out    = (const float*)d_in[7];
    const float* b_out    = (const float*)d_in[8];
    float*       out      = (float*)d_out;
    (void)in_sizes; (void)n_in; (void)out_size;

    static cudaStream_t sA = nullptr;
    static cudaEvent_t  eT, eJ1;
    if (!sA) {
        cudaStreamCreateWithFlags(&sA, cudaStreamNonBlocking);
        cudaEventCreateWithFlags(&eT,  cudaEventDisableTiming);
        cudaEventCreateWithFlags(&eJ1, cudaEventDisableTiming);
        cudaFuncSetAttribute(k_level5v, cudaFuncAttributeMaxDynamicSharedMemorySize, SMEM_L5);
    }
    cudaStream_t s0 = 0;

    k_prep<<<48, 256, 0, s0>>>(W_in, U, W_out);
    // critical path: Pb, T only
    k_vocab1<<<500, 256, SMEM_BYTES, s0>>>(emb, b_in);
    cudaEventRecord(eT, s0);

    // side stream A: Q = T@W_out, then leaf outputs
    cudaStreamWaitEvent(sA, eT, 0);
    k_vocab2<<<500, 256, SMEM_BYTES, sA>>>();
    k_out_leaf<<<8192, 256, 0, sA>>>(x, mask, b_out, out);
    cudaEventRecord(eJ1, sA);

    // critical path: level 5 hidden + fused out rows 4681..37449
    k_level5v<<<1024, 256, SMEM_L5, s0>>>(4681, x, mask, children, b_out, out);

    // critical path: L4..L0, then output head
    k_nodes<<<256, 256, 0, s0>>>(585, 4096, x, mask, children, U); // L4
    k_nodes<<< 32, 256, 0, s0>>>( 73,  512, x, mask, children, U); // L3
    k_tail <<<  1, 256, 0, s0>>>(x, mask, children, U);            // L2..L0
    k_out_t<<<74, 256, SMEM_BYTES, s0>>>(0, 4681, b_out, out);     // out rows 0..4681

    cudaStreamWaitEvent(s0, eJ1, 0);
}

// round 17
// speedup vs baseline: 1.8162x; 1.8162x over previous
#include <cuda_runtime.h>
#include <cuda_fp16.h>
#include <math.h>
#include <stdint.h>

#define NINT 37449
#define NVOC 32000

// ---------------- device scratch (no allocs allowed) ----------------
static __device__ __half g_Pbh[(size_t)NVOC * 128]; // emb@W_in + b_in   (fp16)
static __device__ __half g_Th [(size_t)NVOC * 128]; // tanh(Pb)          (fp16)
static __device__ __half g_Qh [(size_t)NVOC * 128]; // T@W_out           (fp16)
static __device__ __half g_hh [(size_t)NINT * 128]; // hidden, internal  (fp16)
static __device__ uint2  g_BfragS[3][4096];         // {Win,U,Wout}: single fp16 frags

// smem: AsH[64][68] packed fp16x2
#define KP 68
#define SMEM_BYTES (64 * KP * 4)   // 17408

__device__ __forceinline__ uint32_t pack_h2(float v0, float v1) {
    __half2 h = __floats2half2_rn(v0, v1);
    return *(uint32_t*)&h;
}

__device__ __forceinline__ void store_k4h(uint32_t* AsH, int row, int f4, float4 v) {
    const int o = row * KP + f4 * 2;
    AsH[o]     = pack_h2(v.x, v.y);
    AsH[o + 1] = pack_h2(v.z, v.w);
}

__device__ __forceinline__ void mma16h(float d[4], const uint32_t a[4],
                                       uint32_t b0, uint32_t b1) {
    asm volatile(
        "mma.sync.aligned.m16n8k16.row.col.f32.f16.f16.f32 "
        "{%0,%1,%2,%3}, {%4,%5,%6,%7}, {%8,%9}, {%0,%1,%2,%3};"
        : "+f"(d[0]), "+f"(d[1]), "+f"(d[2]), "+f"(d[3])
        : "r"(a[0]), "r"(a[1]), "r"(a[2]), "r"(a[3]), "r"(b0), "r"(b1));
}

// 64x128x128 tile GEMM, fp16: single A x single B. 1 MMA per (ks,nt).
__device__ __forceinline__ void gemm64s(const uint32_t* __restrict__ AsH,
                                        const uint2* __restrict__ Bf,
                                        int wr, int wc, int lane,
                                        float acc[8][4])
{
    const int rA = wr * 16 + (lane >> 2);
    const int cA = lane & 3;
#pragma unroll
    for (int ks = 0; ks < 8; ks++) {
        uint32_t ah[4];
        const int kpb = ks * 8 + cA;
        ah[0] = AsH[rA * KP + kpb];
        ah[1] = AsH[(rA + 8) * KP + kpb];
        ah[2] = AsH[rA * KP + kpb + 4];
        ah[3] = AsH[(rA + 8) * KP + kpb + 4];
#pragma unroll
        for (int nt = 0; nt < 8; nt++) {
            uint2 b = __ldg(&Bf[(ks * 16 + wc * 8 + nt) * 32 + lane]);
            mma16h(acc[nt], ah, b.x, b.y);
        }
    }
}

#define ACC_ZERO8(acc) do { \
    _Pragma("unroll") for (int _b = 0; _b < 8; _b++) \
    _Pragma("unroll") for (int _c = 0; _c < 4; _c++) acc[_b][_c] = 0.f; } while (0)

// ---------------------------------------------------------------------------
// k_prep: single-fp16 B fragments for all three weights (B[n][k] = W[k][n]).
// ---------------------------------------------------------------------------
__global__ void k_prep(const float* __restrict__ Win, const float* __restrict__ U,
                       const float* __restrict__ Wout)
{
    int i = blockIdx.x * 256 + threadIdx.x;
    if (i < 3 * 4096) {
        int w = i >> 12, r = i & 4095;
        int ks = r >> 9, ng = (r >> 5) & 15, lane = r & 31;
        int n = ng * 8 + (lane >> 2);
        int k0 = ks * 16 + (lane & 3) * 2;
        const float* W = (w == 0) ? Win : ((w == 1) ? U : Wout);
        float v00 = W[k0 * 128 + n],       v01 = W[(k0 + 1) * 128 + n];
        float v10 = W[(k0 + 8) * 128 + n], v11 = W[(k0 + 9) * 128 + n];
        g_BfragS[w][r] = make_uint2(pack_h2(v00, v01), pack_h2(v10, v11));
    }
}

// ---------------------------------------------------------------------------
// k_vocab1: Pb = emb@W_in + b_in; T = tanh(Pb)   (64 rows/block)
// ---------------------------------------------------------------------------
__global__ void __launch_bounds__(256, 3)
k_vocab1(const float* __restrict__ emb, const float* __restrict__ b_in)
{
    extern __shared__ uint32_t sm[];
    uint32_t* AsH = sm;

    const int tid = threadIdx.x, wid = tid >> 5, lane = tid & 31;
    const int wr = wid & 3, wc = wid >> 2;
    const int row0 = blockIdx.x * 64;

    for (int i = tid; i < 2048; i += 256) {
        int row = i >> 5, q = i & 31;
        float4 v = ((const float4*)emb)[(size_t)(row0 + row) * 32 + q];
        store_k4h(AsH, row, q, v);
    }
    __syncthreads();

    float acc[8][4];
    ACC_ZERO8(acc);
    gemm64s(AsH, g_BfragS[0], wr, wc, lane, acc);

#pragma unroll
    for (int h = 0; h < 2; h++) {
        const size_t node = row0 + wr * 16 + (lane >> 2) + h * 8;
#pragma unroll
        for (int nt = 0; nt < 8; nt++) {
            const int col = wc * 64 + nt * 8 + (lane & 3) * 2;
            float2 b = *(const float2*)&b_in[col];
            float p0 = acc[nt][h * 2]     + b.x;
            float p1 = acc[nt][h * 2 + 1] + b.y;
            *(__half2*)&g_Pbh[node * 128 + col] = __floats2half2_rn(p0, p1);
            *(__half2*)&g_Th[node * 128 + col] =
                __floats2half2_rn(tanhf(p0), tanhf(p1));
        }
    }
}

// ---------------------------------------------------------------------------
// k_vocab2: Q = T @ W_out  (A staging = straight fp16 row copy)
// ---------------------------------------------------------------------------
__global__ void __launch_bounds__(256, 3)
k_vocab2()
{
    extern __shared__ uint32_t sm[];
    uint32_t* AsH = sm;

    const int tid = threadIdx.x, wid = tid >> 5, lane = tid & 31;
    const int wr = wid & 3, wc = wid >> 2;
    const int row0 = blockIdx.x * 64;

    for (int i = tid; i < 2048; i += 256) {
        int row = i >> 5, q = i & 31;
        uint2 v = ((const uint2*)(g_Th + (size_t)(row0 + row) * 128))[q];
        AsH[row * KP + q * 2]     = v.x;
        AsH[row * KP + q * 2 + 1] = v.y;
    }
    __syncthreads();

    float acc[8][4];
    ACC_ZERO8(acc);
    gemm64s(AsH, g_BfragS[2], wr, wc, lane, acc);

#pragma unroll
    for (int h = 0; h < 2; h++) {
        const size_t node = row0 + wr * 16 + (lane >> 2) + h * 8;
#pragma unroll
        for (int nt = 0; nt < 8; nt++) {
            const int col = wc * 64 + nt * 8 + (lane & 3) * 2;
            *(__half2*)&g_Qh[node * 128 + col] =
                __floats2half2_rn(acc[nt][h * 2], acc[nt][h * 2 + 1]);
        }
    }
}

// ---------------------------------------------------------------------------
// k_level5f: h = tanh(Pb[x*m]*m + (sum_c m_c*T[x_c]) @ U); write g_hh; then
//            FUSED out[node] = h @ W_out + b_out.   64 rows/block.
// Staging accumulates children directly in half2 (HFMA2, no converts).
// ---------------------------------------------------------------------------
__global__ void __launch_bounds__(256, 3)
k_level5f(int s, const int* __restrict__ x, const int* __restrict__ mask,
          const int* __restrict__ children, const float* __restrict__ b_out,
          float* __restrict__ out)
{
    extern __shared__ uint32_t sm[];
    uint32_t* AsH = sm;

    const int tid = threadIdx.x, wid = tid >> 5, lane = tid & 31;
    const int wr = wid & 3, wc = wid >> 2;
    const int row0 = blockIdx.x * 64;

    {
        const int row = tid >> 2, q4 = tid & 3;
        const int node = s + row0 + row;
        const __half* tp[8];
        __half2 fm2[8];
#pragma unroll
        for (int c = 0; c < 8; c++) {
            const int cc = children[(size_t)node * 8 + c];
            const int mm = mask[cc];
            tp[c] = g_Th + (size_t)(x[cc] * mm) * 128;
            fm2[c] = __float2half2_rn((float)mm);
        }
        const __half2 z = __float2half2_rn(0.f);
#pragma unroll
        for (int j = 0; j < 4; j++) {
            const int cid = j * 4 + q4;      // 16-byte chunk = 8 halves
            __half2 a0 = z, a1 = z, a2 = z, a3 = z;
#pragma unroll
            for (int c = 0; c < 8; c++) {
                uint4 w = *(const uint4*)(tp[c] + cid * 8);
                a0 = __hfma2(*(const __half2*)&w.x, fm2[c], a0);
                a1 = __hfma2(*(const __half2*)&w.y, fm2[c], a1);
                a2 = __hfma2(*(const __half2*)&w.z, fm2[c], a2);
                a3 = __hfma2(*(const __half2*)&w.w, fm2[c], a3);
            }
            const int o = row * KP + cid * 4;
            AsH[o]     = *(uint32_t*)&a0;
            AsH[o + 1] = *(uint32_t*)&a1;
            AsH[o + 2] = *(uint32_t*)&a2;
            AsH[o + 3] = *(uint32_t*)&a3;
        }
    }
    __syncthreads();

    float acc[8][4];
    ACC_ZERO8(acc);
    gemm64s(AsH, g_BfragS[1], wr, wc, lane, acc);

    // epilogue 1: h = tanh(acc + Pb*m); write g_hh; keep h in acc
#pragma unroll
    for (int h = 0; h < 2; h++) {
        const int node = s + row0 + wr * 16 + (lane >> 2) + h * 8;
        const float mf = (float)mask[node];
        const size_t xm = (size_t)(x[node] * mask[node]);
#pragma unroll
        for (int nt = 0; nt < 8; nt++) {
            const int col = wc * 64 + nt * 8 + (lane & 3) * 2;
            float2 p = __half22float2(*(const __half2*)&g_Pbh[xm * 128 + col]);
            float o0 = tanhf(acc[nt][h * 2]     + p.x * mf);
            float o1 = tanhf(acc[nt][h * 2 + 1] + p.y * mf);
            *(__half2*)&g_hh[(size_t)node * 128 + col] = __floats2half2_rn(o0, o1);
            acc[nt][h * 2]     = o0;
            acc[nt][h * 2 + 1] = o1;
        }
    }
    __syncthreads();   // all warps done reading AsH in pass 1
#pragma unroll
    for (int h = 0; h < 2; h++) {
        const int r = wr * 16 + (lane >> 2) + h * 8;
#pragma unroll
        for (int nt = 0; nt < 8; nt++) {
            const int col = wc * 64 + nt * 8 + (lane & 3) * 2;
            AsH[r * KP + (col >> 1)] = pack_h2(acc[nt][h * 2], acc[nt][h * 2 + 1]);
        }
    }
    __syncthreads();

    // pass 2: out = h @ W_out + b_out
    ACC_ZERO8(acc);
    gemm64s(AsH, g_BfragS[2], wr, wc, lane, acc);

#pragma unroll
    for (int h = 0; h < 2; h++) {
        const int node = s + row0 + wr * 16 + (lane >> 2) + h * 8;
#pragma unroll
        for (int nt = 0; nt < 8; nt++) {
            const int col = wc * 64 + nt * 8 + (lane & 3) * 2;
            float2 b = *(const float2*)&b_out[col];
            float2 o = make_float2(acc[nt][h * 2] + b.x,
                                   acc[nt][h * 2 + 1] + b.y);
            __stcs((float2*)&out[(size_t)node * 128 + col], o);
        }
    }
}

// ---------------------------------------------------------------------------
// k_out_t: out[r0 .. r0+nrows) = g_hh @ W_out + b_out
// ---------------------------------------------------------------------------
__global__ void __launch_bounds__(256, 3)
k_out_t(int r0, int nrows, const float* __restrict__ b_out, float* __restrict__ out)
{
    extern __shared__ uint32_t sm[];
    uint32_t* AsH = sm;

    const int tid = threadIdx.x, wid = tid >> 5, lane = tid & 31;
    const int wr = wid & 3, wc = wid >> 2;
    const int row0 = r0 + blockIdx.x * 64;
    const int e = r0 + nrows;

    for (int i = tid; i < 2048; i += 256) {
        int row = i >> 5, q = i & 31;
        int rr = row0 + row; if (rr >= e) rr = e - 1;
        uint2 v = ((const uint2*)(g_hh + (size_t)rr * 128))[q];
        AsH[row * KP + q * 2]     = v.x;
        AsH[row * KP + q * 2 + 1] = v.y;
    }
    __syncthreads();

    float acc[8][4];
    ACC_ZERO8(acc);
    gemm64s(AsH, g_BfragS[2], wr, wc, lane, acc);

#pragma unroll
    for (int h = 0; h < 2; h++) {
        const int node = row0 + wr * 16 + (lane >> 2) + h * 8;
        if (node < e) {
#pragma unroll
            for (int nt = 0; nt < 8; nt++) {
                const int col = wc * 64 + nt * 8 + (lane & 3) * 2;
                float2 b = *(const float2*)&b_out[col];
                float2 o = make_float2(acc[nt][h * 2] + b.x,
                                       acc[nt][h * 2 + 1] + b.y);
                __stcs((float2*)&out[(size_t)node * 128 + col], o);
            }
        }
    }
}

// ---------------------------------------------------------------------------
// node-level FFMA body: 16 nodes per block-slot, 256 threads (fp16 h table)
// ---------------------------------------------------------------------------
__device__ __forceinline__ void nodes_body(int base, int s, int e,
                                           const int* __restrict__ x,
                                           const int* __restrict__ mask,
                                           const int* __restrict__ children,
                                           const float* __restrict__ U,
                                           float (*agg)[128])
{
    const int tid = threadIdx.x;
    const int col = tid & 127, half = tid >> 7;

#pragma unroll
    for (int g = 0; g < 8; g++) {
        const int node = base + half * 8 + g;
        const int nb = (node < e) ? node : s;
        float sum = 0.f;
#pragma unroll
        for (int c = 0; c < 8; c++)
            sum += __half2float(g_hh[(size_t)children[(size_t)nb * 8 + c] * 128 + col]);
        agg[half * 8 + g][col] = sum;
    }
    __syncthreads();

    float acc[8];
#pragma unroll
    for (int g = 0; g < 8; g++) acc[g] = 0.f;
#pragma unroll 4
    for (int k = 0; k < 128; k++) {
        const float u = __ldg(&U[k * 128 + col]);
#pragma unroll
        for (int g = 0; g < 8; g++)
            acc[g] = fmaf(agg[half * 8 + g][k], u, acc[g]);
    }

#pragma unroll
    for (int g = 0; g < 8; g++) {
        const int node = base + half * 8 + g;
        if (node < e) {
            const float mf = (float)mask[node];
            const int xm = x[node] * mask[node];
            const float hin = __half2float(g_Pbh[(size_t)xm * 128 + col]) * mf;
            g_hh[(size_t)node * 128 + col] = __float2half_rn(tanhf(hin + acc[g]));
        }
    }
}

__global__ void __launch_bounds__(256, 4)
k_nodes(int s, int n, const int* __restrict__ x, const int* __restrict__ mask,
        const int* __restrict__ children, const float* __restrict__ U)
{
    __shared__ float agg[16][128];
    nodes_body(s + blockIdx.x * 16, s, s + n, x, mask, children, U, agg);
}

__global__ void __launch_bounds__(256, 1)
k_tail(const int* __restrict__ x, const int* __restrict__ mask,
       const int* __restrict__ children, const float* __restrict__ U)
{
    __shared__ float agg[16][128];
    const int ls[3] = {9, 1, 0};
    const int ln[3] = {64, 8, 1};
    for (int lv = 0; lv < 3; lv++) {
        const int s = ls[lv], e = s + ln[lv];
        for (int base = s; base < e; base += 16) {
            nodes_body(base, s, e, x, mask, children, U, agg);
            __syncthreads();
        }
    }
}

// ---------------------------------------------------------------------------
// k_out_leaf: out[leaf] = mask * Q[x] + b_out   (fp16 Q gather, streaming st)
// ---------------------------------------------------------------------------
__global__ void __launch_bounds__(256)
k_out_leaf(const int* __restrict__ x, const int* __restrict__ mask,
           const float* __restrict__ b_out, float* __restrict__ out)
{
    const float4 bv = ((const float4*)b_out)[threadIdx.x & 31];
    int idx = blockIdx.x * 256 + threadIdx.x;
#pragma unroll
    for (int it = 0; it < 4; it++, idx += 8192 * 256) {
        const int rr = idx >> 5, c = idx & 31;
        const int node = NINT + rr;
        const int m = mask[node];
        const int xm = x[node] * m;
        const float mf = (float)m;
        uint2 qw = *(const uint2*)(g_Qh + (size_t)xm * 128 + c * 4);
        float2 q0 = __half22float2(*(const __half2*)&qw.x);
        float2 q1 = __half22float2(*(const __half2*)&qw.y);
        float4 o = make_float4(fmaf(q0.x, mf, bv.x), fmaf(q0.y, mf, bv.y),
                               fmaf(q1.x, mf, bv.z), fmaf(q1.y, mf, bv.w));
        __stcs(&((float4*)out)[(size_t)node * 32 + c], o);
    }
}

// ---------------------------------------------------------------------------
extern "C" void kernel_launch(void* const* d_in, const int* in_sizes, int n_in,
                              void* d_out, int out_size)
{
    const int*   x        = (const int*)  d_in[0];
    const int*   mask     = (const int*)  d_in[1];
    const int*   children = (const int*)  d_in[2];
    const float* emb      = (const float*)d_in[3];
    const float* W_in     = (const float*)d_in[4];
    const float* b_in     = (const float*)d_in[5];
    const float* U        = (const float*)d_in[6];
    const float* W_out    = (const float*)d_in[7];
    const float* b_out    = (const float*)d_in[8];
    float*       out      = (float*)d_out;
    (void)in_sizes; (void)n_in; (void)out_size;

    static cudaStream_t sA = nullptr;
    static cudaEvent_t  eT, eJ1;
    if (!sA) {
        cudaStreamCreateWithFlags(&sA, cudaStreamNonBlocking);
        cudaEventCreateWithFlags(&eT,  cudaEventDisableTiming);
        cudaEventCreateWithFlags(&eJ1, cudaEventDisableTiming);
    }
    cudaStream_t s0 = 0;

    k_prep<<<48, 256, 0, s0>>>(W_in, U, W_out);
    // critical path: Pb, T only
    k_vocab1<<<500, 256, SMEM_BYTES, s0>>>(emb, b_in);
    cudaEventRecord(eT, s0);

    // side stream A: Q = T@W_out, then leaf outputs
    cudaStreamWaitEvent(sA, eT, 0);
    k_vocab2<<<500, 256, SMEM_BYTES, sA>>>();
    k_out_leaf<<<8192, 256, 0, sA>>>(x, mask, b_out, out);
    cudaEventRecord(eJ1, sA);

    // critical path: level 5 hidden + fused out rows 4681..37449
    k_level5f<<<512, 256, SMEM_BYTES, s0>>>(4681, x, mask, children, b_out, out);

    // critical path: L4..L0, then output head
    k_nodes<<<256, 256, 0, s0>>>(585, 4096, x, mask, children, U); // L4
    k_nodes<<< 32, 256, 0, s0>>>( 73,  512, x, mask, children, U); // L3
    k_tail <<<  1, 256, 0, s0>>>(x, mask, children, U);            // L2..L0
    k_out_t<<<74, 256, SMEM_BYTES, s0>>>(0, 4681, b_out, out);     // out rows 0..4681

    cudaStreamWaitEvent(s0, eJ1, 0);
}